// round 2
// baseline (speedup 1.0000x reference)
#include <cuda_runtime.h>
#include <math.h>

#define BB 32
#define MM 1024
#define NN 1024
#define SS 8      // n-split factor (n-chunks of 128)
#define TN 128    // n per block tile

typedef unsigned long long u64;

// ---------------- scratch (no allocations allowed) ----------------
__device__ u64   g_Rp[BB * 4 * 12 * 128];   // packed constants: [b][kp][j][t] -> (m=t+2kp*128, m=t+(2kp+1)*128)
__device__ float g_c[BB * MM];
__device__ float g_part[SS][BB * MM];       // partial sqrt-sums per n-chunk (deterministic, no atomics)
__device__ float g_dish[BB * MM];           // sum over all n (not yet /N)
__device__ float g_lpart[128];              // per-block loss partials
__device__ int   g_which[BB];

// ---------------- f32x2 helpers (sm_103a packed fp32) ----------------
__device__ __forceinline__ u64 pack2(float a, float b) {
    u64 r; asm("mov.b64 %0, {%1,%2};" : "=l"(r) : "f"(a), "f"(b)); return r;
}
__device__ __forceinline__ void unpack2(u64 v, float& a, float& b) {
    asm("mov.b64 {%0,%1}, %2;" : "=f"(a), "=f"(b) : "l"(v));
}
__device__ __forceinline__ u64 fma2(u64 a, u64 b, u64 c) {
    u64 r; asm("fma.rn.f32x2 %0, %1, %2, %3;" : "=l"(r) : "l"(a), "l"(b), "l"(c)); return r;
}
__device__ __forceinline__ u64 mul2(u64 a, u64 b) {
    u64 r; asm("mul.rn.f32x2 %0, %1, %2;" : "=l"(r) : "l"(a), "l"(b)); return r;
}
__device__ __forceinline__ float sqrt_approx(float x) {
    float r; asm("sqrt.approx.f32 %0, %1;" : "=f"(r) : "f"(x)); return r;
}

// ---------------- K0: per-(b,m) prep ----------------
__global__ void k_prep(const float* __restrict__ pred_r,
                       const float* __restrict__ pred_t,
                       const float* __restrict__ pred_c,
                       const float* __restrict__ points) {
    int i = blockIdx.x * blockDim.x + threadIdx.x;
    if (i >= BB * MM) return;
    int b = i >> 10, m = i & 1023;

    float qx = pred_r[4 * i + 0], qy = pred_r[4 * i + 1];
    float qz = pred_r[4 * i + 2], qw = pred_r[4 * i + 3];
    float nrm = sqrtf(qx * qx + qy * qy + qz * qz + qw * qw);
    float inv = __fdividef(1.0f, nrm + 1e-8f);
    qx *= inv; qy *= inv; qz *= inv; qw *= inv;

    float R[9];
    R[0] = 1.0f - 2.0f * (qy * qy + qz * qz);
    R[1] = 2.0f * (qx * qy - qz * qw);
    R[2] = 2.0f * (qx * qz + qy * qw);
    R[3] = 2.0f * (qx * qy + qz * qw);
    R[4] = 1.0f - 2.0f * (qx * qx + qz * qz);
    R[5] = 2.0f * (qy * qz - qx * qw);
    R[6] = 2.0f * (qx * qz - qy * qw);
    R[7] = 2.0f * (qy * qz + qx * qw);
    R[8] = 1.0f - 2.0f * (qx * qx + qy * qy);

    float t0 = points[3 * i + 0] + pred_t[3 * i + 0];
    float t1 = points[3 * i + 1] + pred_t[3 * i + 1];
    float t2 = points[3 * i + 2] + pred_t[3 * i + 2];

    g_c[i] = fmaxf(pred_c[i], 1e-6f);

    int tloc = m & 127, k = m >> 7, kp = k >> 1, half = k & 1;
    float* dst = reinterpret_cast<float*>(g_Rp);
    size_t base = ((size_t)(b * 4 + kp) * 12 * 128 + tloc) * 2 + half;
    // j = 0..8 -> R row-major, j = 9..11 -> t
    #pragma unroll
    for (int j = 0; j < 9; j++) dst[base + (size_t)j * 256] = R[j];
    dst[base + 9 * 256]  = t0;
    dst[base + 10 * 256] = t1;
    dst[base + 11 * 256] = t2;
}

// ---------------- K1: main 33.5M-pair distance kernel ----------------
__global__ void __launch_bounds__(128) k_main(const float* __restrict__ mp,
                                              const float* __restrict__ tg) {
    const int s = blockIdx.x;   // n-chunk
    const int b = blockIdx.y;
    const int t = threadIdx.x;  // 0..127

    __shared__ u64 sm[6][TN];   // splatted (v,v): mp.x,mp.y,mp.z,tg.x,tg.y,tg.z

    {
        int n = s * TN + t;
        const float* mpr = mp + ((size_t)b * NN + n) * 3;
        const float* tgr = tg + ((size_t)b * NN + n) * 3;
        float a0 = mpr[0], a1 = mpr[1], a2 = mpr[2];
        float c0 = tgr[0], c1 = tgr[1], c2 = tgr[2];
        sm[0][t] = pack2(a0, a0);
        sm[1][t] = pack2(a1, a1);
        sm[2][t] = pack2(a2, a2);
        sm[3][t] = pack2(c0, c0);
        sm[4][t] = pack2(c1, c1);
        sm[5][t] = pack2(c2, c2);
    }
    __syncthreads();

    // packed constants for 4 m-pair groups (8 m's per thread)
    const u64* rp = g_Rp + (size_t)b * (4 * 12 * 128);
    u64 C[4][12];
    #pragma unroll
    for (int g = 0; g < 4; g++)
        #pragma unroll
        for (int j = 0; j < 12; j++)
            C[g][j] = rp[(size_t)(g * 12 + j) * 128 + t];

    float acc[8];
    #pragma unroll
    for (int a = 0; a < 8; a++) acc[a] = 0.0f;

    const u64 NEG1 = 0xBF800000BF800000ULL; // (-1.0f, -1.0f)

    #pragma unroll 2
    for (int n = 0; n < TN; n++) {
        u64 m0 = sm[0][n], m1 = sm[1][n], m2 = sm[2][n];
        u64 g0 = sm[3][n], g1 = sm[4][n], g2 = sm[5][n];
        #pragma unroll
        for (int g = 0; g < 4; g++) {
            u64 s0 = fma2(g0, NEG1, C[g][9]);   // t - tg
            u64 s1 = fma2(g1, NEG1, C[g][10]);
            u64 s2 = fma2(g2, NEG1, C[g][11]);
            u64 d0 = fma2(m0, C[g][0], fma2(m1, C[g][3], fma2(m2, C[g][6], s0)));
            u64 d1 = fma2(m0, C[g][1], fma2(m1, C[g][4], fma2(m2, C[g][7], s1)));
            u64 d2 = fma2(m0, C[g][2], fma2(m1, C[g][5], fma2(m2, C[g][8], s2)));
            u64 sq = fma2(d0, d0, fma2(d1, d1, mul2(d2, d2)));
            float sa, sb; unpack2(sq, sa, sb);
            acc[2 * g]     += sqrt_approx(sa);
            acc[2 * g + 1] += sqrt_approx(sb);
        }
    }

    #pragma unroll
    for (int g = 0; g < 4; g++) {
        g_part[s][(size_t)b * MM + t + (2 * g) * 128]     = acc[2 * g];
        g_part[s][(size_t)b * MM + t + (2 * g + 1) * 128] = acc[2 * g + 1];
    }
}

// ---------------- K2: per-b argmax of c ----------------
__global__ void k_argmax() {
    int b = blockIdx.x;
    int t = threadIdx.x; // 128
    float best = -1e30f; int bi = 0;
    for (int m = t; m < MM; m += 128) {
        float v = g_c[b * MM + m];
        if (v > best) { best = v; bi = m; }
    }
    __shared__ float sv[128];
    __shared__ int   si[128];
    sv[t] = best; si[t] = bi;
    __syncthreads();
    for (int off = 64; off > 0; off >>= 1) {
        if (t < off) {
            if (sv[t + off] > sv[t] || (sv[t + off] == sv[t] && si[t + off] < si[t])) {
                sv[t] = sv[t + off]; si[t] = si[t + off];
            }
        }
        __syncthreads();
    }
    if (t == 0) g_which[b] = si[0];
}

// ---------------- K2b: combine partials + loss partial reduce ----------------
__global__ void k_combine(const float* __restrict__ wptr) {
    int i = blockIdx.x * 256 + threadIdx.x; // 128 blocks * 256 = 32768
    float w = *wptr;
    float dsum = 0.0f;
    #pragma unroll
    for (int ss = 0; ss < SS; ss++) dsum += g_part[ss][i];
    g_dish[i] = dsum;
    float c = g_c[i];
    float term = dsum * (1.0f / (float)NN) * c - w * logf(c);

    __shared__ float sbuf[256];
    sbuf[threadIdx.x] = term;
    __syncthreads();
    for (int off = 128; off > 0; off >>= 1) {
        if (threadIdx.x < off) sbuf[threadIdx.x] += sbuf[threadIdx.x + off];
        __syncthreads();
    }
    if (threadIdx.x == 0) g_lpart[blockIdx.x] = sbuf[0];
}

// ---------------- K3: transform new_points / new_target ----------------
__global__ void k_transform(const float* __restrict__ points,
                            const float* __restrict__ target,
                            float* __restrict__ out) {
    int id = blockIdx.x * 256 + threadIdx.x; // < 32*2048
    if (id >= BB * (MM + NN)) return;
    int b = id >> 11;
    int r = id & 2047;

    int which = g_which[b];
    int tloc = which & 127, k = which >> 7, kp = k >> 1, half = k & 1;
    const float* rpf = reinterpret_cast<const float*>(g_Rp);
    size_t base = ((size_t)(b * 4 + kp) * 12 * 128 + tloc) * 2 + half;

    float Rb[9], tb[3];
    #pragma unroll
    for (int j = 0; j < 9; j++) Rb[j] = rpf[base + (size_t)j * 256];
    #pragma unroll
    for (int j = 0; j < 3; j++) tb[j] = rpf[base + (size_t)(9 + j) * 256];

    const float* src;
    float* dst;
    if (r < MM) {
        src = points + ((size_t)b * MM + r) * 3;
        dst = out + 2 + ((size_t)b * MM + r) * 3;
    } else {
        int n = r - MM;
        src = target + ((size_t)b * NN + n) * 3;
        dst = out + 2 + (size_t)BB * MM * 3 + ((size_t)b * NN + n) * 3;
    }
    float d0 = src[0] - tb[0];
    float d1 = src[1] - tb[1];
    float d2 = src[2] - tb[2];
    #pragma unroll
    for (int j = 0; j < 3; j++)
        dst[j] = d0 * Rb[0 * 3 + j] + d1 * Rb[1 * 3 + j] + d2 * Rb[2 * 3 + j];
}

// ---------------- K4: final scalars ----------------
__global__ void k_final(float* __restrict__ out) {
    int t = threadIdx.x; // 128
    __shared__ float sbuf[128];
    sbuf[t] = g_lpart[t];
    __syncthreads();
    for (int off = 64; off > 0; off >>= 1) {
        if (t < off) sbuf[t] += sbuf[t + off];
        __syncthreads();
    }
    if (t == 0) {
        float loss = sbuf[0] / (float)(BB * MM);
        float db = 0.0f;
        for (int b = 0; b < BB; b++) db += g_dish[b * MM + g_which[b]];
        out[0] = loss;
        out[1] = db * (1.0f / (float)NN) / (float)BB;
    }
}

// ---------------- launch ----------------
extern "C" void kernel_launch(void* const* d_in, const int* in_sizes, int n_in,
                              void* d_out, int out_size) {
    const float* pred_r       = (const float*)d_in[0];
    const float* pred_t       = (const float*)d_in[1];
    const float* pred_c       = (const float*)d_in[2];
    const float* target       = (const float*)d_in[3];
    const float* model_points = (const float*)d_in[4];
    // d_in[5] = idx (unused, refine path)
    const float* points       = (const float*)d_in[6];
    const float* wptr         = (const float*)d_in[7];
    // d_in[8] = refine (unused)
    float* out = (float*)d_out;

    k_prep<<<128, 256>>>(pred_r, pred_t, pred_c, points);
    k_main<<<dim3(SS, BB), 128>>>(model_points, target);
    k_argmax<<<BB, 128>>>();
    k_combine<<<128, 256>>>(wptr);
    k_transform<<<256, 256>>>(points, target, out);
    k_final<<<1, 128>>>(out);
}

// round 3
// speedup vs baseline: 1.3478x; 1.3478x over previous
#include <cuda_runtime.h>
#include <math.h>

#define BB 32
#define MM 1024
#define NN 1024
#define SS 16     // n-split factor
#define TN 64     // n per block tile (SS*TN = NN)
#define MS 2      // m-split factor (2 groups of pairs per thread)

typedef unsigned long long u64;

// ---------------- scratch (no allocations allowed) ----------------
__device__ u64   g_Rp[BB * 4 * 12 * 128];   // packed: [b][kp][j][t] -> (m=t+2kp*128, m=t+(2kp+1)*128)
__device__ float g_c[BB * MM];
__device__ float g_part[SS][BB * MM];       // partial sqrt-sums per n-chunk
__device__ float g_dish[BB * MM];           // sum over all n (not yet /N)
__device__ float g_lpart[256];              // per-block loss partials
__device__ float g_amaxv[128];              // per-prep-block argmax partials (4 per b)
__device__ int   g_amaxi[128];
__device__ int   g_which[BB];

// ---------------- f32x2 helpers (sm_103a packed fp32) ----------------
__device__ __forceinline__ u64 pack2(float a, float b) {
    u64 r; asm("mov.b64 %0, {%1,%2};" : "=l"(r) : "f"(a), "f"(b)); return r;
}
__device__ __forceinline__ void unpack2(u64 v, float& a, float& b) {
    asm("mov.b64 {%0,%1}, %2;" : "=f"(a), "=f"(b) : "l"(v));
}
__device__ __forceinline__ u64 fma2(u64 a, u64 b, u64 c) {
    u64 r; asm("fma.rn.f32x2 %0, %1, %2, %3;" : "=l"(r) : "l"(a), "l"(b), "l"(c)); return r;
}
__device__ __forceinline__ u64 mul2(u64 a, u64 b) {
    u64 r; asm("mul.rn.f32x2 %0, %1, %2;" : "=l"(r) : "l"(a), "l"(b)); return r;
}
__device__ __forceinline__ float sqrt_approx(float x) {
    float r; asm("sqrt.approx.f32 %0, %1;" : "=f"(r) : "f"(x)); return r;
}

// ---------------- K0: per-(b,m) prep + per-block argmax partials ----------------
__global__ void k_prep(const float* __restrict__ pred_r,
                       const float* __restrict__ pred_t,
                       const float* __restrict__ pred_c,
                       const float* __restrict__ points) {
    int i = blockIdx.x * 256 + threadIdx.x;   // 128 blocks x 256
    int b = i >> 10, m = i & 1023;

    float qx = pred_r[4 * i + 0], qy = pred_r[4 * i + 1];
    float qz = pred_r[4 * i + 2], qw = pred_r[4 * i + 3];
    float nrm = sqrtf(qx * qx + qy * qy + qz * qz + qw * qw);
    float inv = __fdividef(1.0f, nrm + 1e-8f);
    qx *= inv; qy *= inv; qz *= inv; qw *= inv;

    float R[9];
    R[0] = 1.0f - 2.0f * (qy * qy + qz * qz);
    R[1] = 2.0f * (qx * qy - qz * qw);
    R[2] = 2.0f * (qx * qz + qy * qw);
    R[3] = 2.0f * (qx * qy + qz * qw);
    R[4] = 1.0f - 2.0f * (qx * qx + qz * qz);
    R[5] = 2.0f * (qy * qz - qx * qw);
    R[6] = 2.0f * (qx * qz - qy * qw);
    R[7] = 2.0f * (qy * qz + qx * qw);
    R[8] = 1.0f - 2.0f * (qx * qx + qy * qy);

    float t0 = points[3 * i + 0] + pred_t[3 * i + 0];
    float t1 = points[3 * i + 1] + pred_t[3 * i + 1];
    float t2 = points[3 * i + 2] + pred_t[3 * i + 2];

    float c = fmaxf(pred_c[i], 1e-6f);
    g_c[i] = c;

    int tloc = m & 127, k = m >> 7, kp = k >> 1, half = k & 1;
    float* dst = reinterpret_cast<float*>(g_Rp);
    size_t base = ((size_t)(b * 4 + kp) * 12 * 128 + tloc) * 2 + half;
    #pragma unroll
    for (int j = 0; j < 9; j++) dst[base + (size_t)j * 256] = R[j];
    dst[base + 9 * 256]  = t0;
    dst[base + 10 * 256] = t1;
    dst[base + 11 * 256] = t2;

    // block argmax partial of pred_c (clamp monotone; max > 1e-6 so argmax unchanged)
    __shared__ float sv[256];
    __shared__ int   si[256];
    int tt = threadIdx.x;
    sv[tt] = c; si[tt] = m;
    __syncthreads();
    #pragma unroll
    for (int off = 128; off > 0; off >>= 1) {
        if (tt < off) {
            if (sv[tt + off] > sv[tt] || (sv[tt + off] == sv[tt] && si[tt + off] < si[tt])) {
                sv[tt] = sv[tt + off]; si[tt] = si[tt + off];
            }
        }
        __syncthreads();
    }
    if (tt == 0) { g_amaxv[blockIdx.x] = sv[0]; g_amaxi[blockIdx.x] = si[0]; }
}

// ---------------- K1: main 33.5M-pair distance kernel ----------------
// grid (SS, MS, BB), 128 threads; 2 pair-groups (4 m's) per thread, n-tile TN.
__global__ void __launch_bounds__(128) k_main(const float* __restrict__ mp,
                                              const float* __restrict__ tg) {
    const int s = blockIdx.x;
    const int h = blockIdx.y;
    const int b = blockIdx.z;
    const int t = threadIdx.x;

    __shared__ u64 sm[6][TN];   // splatted (v,v): mp.x,y,z, tg.x,y,z

    if (t < TN) {
        int n = s * TN + t;
        const float* mpr = mp + ((size_t)b * NN + n) * 3;
        const float* tgr = tg + ((size_t)b * NN + n) * 3;
        float a0 = mpr[0], a1 = mpr[1], a2 = mpr[2];
        float c0 = tgr[0], c1 = tgr[1], c2 = tgr[2];
        sm[0][t] = pack2(a0, a0);
        sm[1][t] = pack2(a1, a1);
        sm[2][t] = pack2(a2, a2);
        sm[3][t] = pack2(c0, c0);
        sm[4][t] = pack2(c1, c1);
        sm[5][t] = pack2(c2, c2);
    }
    __syncthreads();

    const u64* rp = g_Rp + (size_t)b * (4 * 12 * 128);
    u64 C[2][12];
    #pragma unroll
    for (int g = 0; g < 2; g++)
        #pragma unroll
        for (int j = 0; j < 12; j++)
            C[g][j] = rp[(size_t)((2 * h + g) * 12 + j) * 128 + t];

    float acc[4];
    #pragma unroll
    for (int a = 0; a < 4; a++) acc[a] = 0.0f;

    const u64 NEG1 = 0xBF800000BF800000ULL;

    #pragma unroll 4
    for (int n = 0; n < TN; n++) {
        u64 m0 = sm[0][n], m1 = sm[1][n], m2 = sm[2][n];
        u64 v0 = sm[3][n], v1 = sm[4][n], v2 = sm[5][n];
        #pragma unroll
        for (int g = 0; g < 2; g++) {
            u64 s0 = fma2(v0, NEG1, C[g][9]);
            u64 s1 = fma2(v1, NEG1, C[g][10]);
            u64 s2 = fma2(v2, NEG1, C[g][11]);
            u64 d0 = fma2(m0, C[g][0], fma2(m1, C[g][3], fma2(m2, C[g][6], s0)));
            u64 d1 = fma2(m0, C[g][1], fma2(m1, C[g][4], fma2(m2, C[g][7], s1)));
            u64 d2 = fma2(m0, C[g][2], fma2(m1, C[g][5], fma2(m2, C[g][8], s2)));
            u64 sq = fma2(d0, d0, fma2(d1, d1, mul2(d2, d2)));
            float sa, sb; unpack2(sq, sa, sb);
            acc[2 * g]     += sqrt_approx(sa);
            acc[2 * g + 1] += sqrt_approx(sb);
        }
    }

    #pragma unroll
    for (int g = 0; g < 2; g++) {
        int m0i = t + (4 * h + 2 * g) * 128;
        g_part[s][(size_t)b * MM + m0i]       = acc[2 * g];
        g_part[s][(size_t)b * MM + m0i + 128] = acc[2 * g + 1];
    }
}

// ---------------- K2: combine partials + loss partials + argmax finish ----------------
__global__ void k_combine(const float* __restrict__ wptr) {
    if (blockIdx.x == 256) {
        // argmax finish: thread t<32 handles b=t, scans its 4 prep-block partials in order
        int t = threadIdx.x;
        if (t < BB) {
            float best = -1e30f; int bi = 0;
            #pragma unroll
            for (int j = 0; j < 4; j++) {
                float v = g_amaxv[t * 4 + j];
                int   i = g_amaxi[t * 4 + j];
                if (v > best) { best = v; bi = i; }
            }
            g_which[t] = bi;
        }
        return;
    }
    int i = blockIdx.x * 128 + threadIdx.x;  // 256 blocks x 128 = 32768
    float w = *wptr;
    float dsum = 0.0f;
    #pragma unroll
    for (int ss = 0; ss < SS; ss++) dsum += g_part[ss][i];
    g_dish[i] = dsum;
    float c = g_c[i];
    float term = dsum * (1.0f / (float)NN) * c - w * __logf(c);

    __shared__ float sbuf[128];
    int t = threadIdx.x;
    sbuf[t] = term;
    __syncthreads();
    #pragma unroll
    for (int off = 64; off > 0; off >>= 1) {
        if (t < off) sbuf[t] += sbuf[t + off];
        __syncthreads();
    }
    if (t == 0) g_lpart[blockIdx.x] = sbuf[0];
}

// ---------------- K3: transform new_points / new_target + final scalars ----------------
__global__ void k_transform(const float* __restrict__ points,
                            const float* __restrict__ target,
                            float* __restrict__ out) {
    if (blockIdx.x == 256) {
        // final scalars
        int t = threadIdx.x;
        __shared__ float sbuf[128];
        if (t < 128) sbuf[t] = g_lpart[t] + g_lpart[t + 128];
        __syncthreads();
        #pragma unroll
        for (int off = 64; off > 0; off >>= 1) {
            if (t < off) sbuf[t] += sbuf[t + off];
            __syncthreads();
        }
        if (t == 0) {
            float loss = sbuf[0] / (float)(BB * MM);
            float db = 0.0f;
            for (int b = 0; b < BB; b++) db += g_dish[b * MM + g_which[b]];
            out[0] = loss;
            out[1] = db * (1.0f / (float)NN) / (float)BB;
        }
        return;
    }
    int id = blockIdx.x * 256 + threadIdx.x; // 256 blocks x 256 = 65536 = BB*(MM+NN)
    int b = id >> 11;
    int r = id & 2047;

    int which = g_which[b];
    int tloc = which & 127, k = which >> 7, kp = k >> 1, half = k & 1;
    const float* rpf = reinterpret_cast<const float*>(g_Rp);
    size_t base = ((size_t)(b * 4 + kp) * 12 * 128 + tloc) * 2 + half;

    float Rb[9], tb[3];
    #pragma unroll
    for (int j = 0; j < 9; j++) Rb[j] = rpf[base + (size_t)j * 256];
    #pragma unroll
    for (int j = 0; j < 3; j++) tb[j] = rpf[base + (size_t)(9 + j) * 256];

    const float* src;
    float* dst;
    if (r < MM) {
        src = points + ((size_t)b * MM + r) * 3;
        dst = out + 2 + ((size_t)b * MM + r) * 3;
    } else {
        int n = r - MM;
        src = target + ((size_t)b * NN + n) * 3;
        dst = out + 2 + (size_t)BB * MM * 3 + ((size_t)b * NN + n) * 3;
    }
    float d0 = src[0] - tb[0];
    float d1 = src[1] - tb[1];
    float d2 = src[2] - tb[2];
    #pragma unroll
    for (int j = 0; j < 3; j++)
        dst[j] = d0 * Rb[0 * 3 + j] + d1 * Rb[1 * 3 + j] + d2 * Rb[2 * 3 + j];
}

// ---------------- launch ----------------
extern "C" void kernel_launch(void* const* d_in, const int* in_sizes, int n_in,
                              void* d_out, int out_size) {
    const float* pred_r       = (const float*)d_in[0];
    const float* pred_t       = (const float*)d_in[1];
    const float* pred_c       = (const float*)d_in[2];
    const float* target       = (const float*)d_in[3];
    const float* model_points = (const float*)d_in[4];
    // d_in[5] = idx (unused, refine path)
    const float* points       = (const float*)d_in[6];
    const float* wptr         = (const float*)d_in[7];
    // d_in[8] = refine (unused)
    float* out = (float*)d_out;

    k_prep<<<128, 256>>>(pred_r, pred_t, pred_c, points);
    k_main<<<dim3(SS, MS, BB), 128>>>(model_points, target);
    k_combine<<<257, 128>>>(wptr);
    k_transform<<<257, 256>>>(points, target, out);
}